// round 5
// baseline (speedup 1.0000x reference)
#include <cuda_runtime.h>

// GRU_8211977470410 — bidirectional GRU (H=32, in=1), B=2048, T=512, MLP head.
// Backward direction collapses to ONE step (scan reverse=True: ys_b[-1] = GRU(0, x[T-1])).
// 1 warp = 2 batch rows; lane = hidden unit; W_hh rows in regs as f32x2;
// 12 independent 8-deep fma.rn.f32x2 chains; f32x2 gate epilogue (both batches packed);
// parity double-buffered smem h-exchange with a single __syncwarp per step.

#define HDIM 32
#define FULLMASK 0xffffffffu
typedef unsigned long long u64;

__device__ __forceinline__ u64 pack2(float lo, float hi) {
    u64 d; asm("mov.b64 %0, {%1, %2};" : "=l"(d) : "f"(lo), "f"(hi)); return d;
}
__device__ __forceinline__ void unpack2(u64 v, float& lo, float& hi) {
    asm("mov.b64 {%0, %1}, %2;" : "=f"(lo), "=f"(hi) : "l"(v));
}
__device__ __forceinline__ u64 ffma2(u64 a, u64 b, u64 c) {
    u64 d; asm("fma.rn.f32x2 %0, %1, %2, %3;" : "=l"(d) : "l"(a), "l"(b), "l"(c)); return d;
}
__device__ __forceinline__ u64 fadd2(u64 a, u64 b) {
    u64 d; asm("add.rn.f32x2 %0, %1, %2;" : "=l"(d) : "l"(a), "l"(b)); return d;
}
__device__ __forceinline__ u64 fmul2(u64 a, u64 b) {
    u64 d; asm("mul.rn.f32x2 %0, %1, %2;" : "=l"(d) : "l"(a), "l"(b)); return d;
}
__device__ __forceinline__ float ex2f(float x) {
    float r; asm("ex2.approx.f32 %0, %1;" : "=f"(r) : "f"(x)); return r;
}
__device__ __forceinline__ float rcpf(float x) {
    float r; asm("rcp.approx.f32 %0, %1;" : "=f"(r) : "f"(x)); return r;
}
__device__ __forceinline__ float sigm(float x) {
    return __fdividef(1.0f, 1.0f + __expf(-x));
}
__device__ __forceinline__ float tanh_fast(float x) {
    float e = __expf(2.0f * x);
    return 1.0f - __fdividef(2.0f, e + 1.0f);
}

__global__ void __launch_bounds__(32)
gru_bidir_kernel(const float* __restrict__ x,
                 const float* __restrict__ Wih_f, const float* __restrict__ Whh_f,
                 const float* __restrict__ bih_f, const float* __restrict__ bhh_f,
                 const float* __restrict__ Wih_b, const float* __restrict__ bih_b,
                 const float* __restrict__ bhh_b,
                 const float* __restrict__ W1, const float* __restrict__ b1v,
                 const float* __restrict__ W2, const float* __restrict__ b2v,
                 float* __restrict__ out, int B, int T)
{
    __shared__ __align__(16) float xch[2][2][32];   // [parity][batch][lane] h exchange
    __shared__ __align__(16) float scr[2][80];      // head scratch: concat(64) + h1(16)

    const int lane = threadIdx.x;
    const int bA = blockIdx.x * 2;
    const int bB = bA + 1;
    const bool has2 = (bB < B);
    const int rr = lane, rz = lane + HDIM, rn = lane + 2 * HDIM;

    // ---- forward W_hh rows (r,z,n for this lane) as packed f32x2 ----
    u64 wr[16], wz[16], wn[16];
    {
        const float4* pr = reinterpret_cast<const float4*>(Whh_f + rr * HDIM);
        const float4* pz = reinterpret_cast<const float4*>(Whh_f + rz * HDIM);
        const float4* pn = reinterpret_cast<const float4*>(Whh_f + rn * HDIM);
#pragma unroll
        for (int i = 0; i < 8; i++) {
            float4 a = pr[i]; wr[2*i] = pack2(a.x, a.y); wr[2*i+1] = pack2(a.z, a.w);
            float4 c = pz[i]; wz[2*i] = pack2(c.x, c.y); wz[2*i+1] = pack2(c.z, c.w);
            float4 d = pn[i]; wn[2*i] = pack2(d.x, d.y); wn[2*i+1] = pack2(d.z, d.w);
        }
    }

    const float L2E = 1.4426950408889634f;
    const u64 one2    = pack2(1.0f, 1.0f);
    const u64 negl2e2 = pack2(-L2E, -L2E);
    const u64 twol2e2 = pack2(2.0f * L2E, 2.0f * L2E);
    const u64 negtwo2 = pack2(-2.0f, -2.0f);

    const float wirS = Wih_f[rr], wizS = Wih_f[rz], winS = Wih_f[rn];
    const u64 wir2 = pack2(wirS, wirS);
    const u64 wiz2 = pack2(wizS, wizS);
    const u64 win2 = pack2(winS, winS);
    const u64 bin2 = pack2(bih_f[rn], bih_f[rn]);
    // fold b_ih into accumulator init for r,z (their preact is a plain sum);
    // n-gate keeps b_hh inside (multiplied by r) and b_ih outside.
    const u64 accR0 = pack2(bhh_f[rr] + bih_f[rr], 0.0f);
    const u64 accZ0 = pack2(bhh_f[rz] + bih_f[rz], 0.0f);
    const u64 accN0 = pack2(bhh_f[rn], 0.0f);

    const float* xA = x + (size_t)bA * T;
    const float* xB = x + (size_t)(has2 ? bB : bA) * T;

    u64 h0[16], h1[16];
#pragma unroll
    for (int i = 0; i < 16; i++) { h0[i] = 0ull; h1[i] = 0ull; }
    u64 hs2 = 0ull;   // packed (hsA, hsB)

    auto step = [&](float xav, float xbv, int p) {
        // ---- hidden matvec: 12 independent 8-deep FFMA2 chains ----
        u64 Ar0 = accR0, Ar1 = 0ull, Az0 = accZ0, Az1 = 0ull, An0 = accN0, An1 = 0ull;
        u64 Br0 = accR0, Br1 = 0ull, Bz0 = accZ0, Bz1 = 0ull, Bn0 = accN0, Bn1 = 0ull;
#pragma unroll
        for (int i = 0; i < 8; i++) {
            Ar0 = ffma2(wr[i], h0[i], Ar0);     Ar1 = ffma2(wr[i+8], h0[i+8], Ar1);
            Br0 = ffma2(wr[i], h1[i], Br0);     Br1 = ffma2(wr[i+8], h1[i+8], Br1);
            Az0 = ffma2(wz[i], h0[i], Az0);     Az1 = ffma2(wz[i+8], h0[i+8], Az1);
            Bz0 = ffma2(wz[i], h1[i], Bz0);     Bz1 = ffma2(wz[i+8], h1[i+8], Bz1);
            An0 = ffma2(wn[i], h0[i], An0);     An1 = ffma2(wn[i+8], h0[i+8], An1);
            Bn0 = ffma2(wn[i], h1[i], Bn0);     Bn1 = ffma2(wn[i+8], h1[i+8], Bn1);
        }
        float lo, hi; u64 s;
        s = fadd2(Ar0, Ar1); unpack2(s, lo, hi); float hrA = lo + hi;
        s = fadd2(Br0, Br1); unpack2(s, lo, hi); float hrB = lo + hi;
        s = fadd2(Az0, Az1); unpack2(s, lo, hi); float hzA = lo + hi;
        s = fadd2(Bz0, Bz1); unpack2(s, lo, hi); float hzB = lo + hi;
        s = fadd2(An0, An1); unpack2(s, lo, hi); float hnA = lo + hi;
        s = fadd2(Bn0, Bn1); unpack2(s, lo, hi); float hnB = lo + hi;

        const u64 x2  = pack2(xav, xbv);
        const u64 hr2 = pack2(hrA, hrB);
        const u64 hz2 = pack2(hzA, hzB);
        const u64 hn2 = pack2(hnA, hnB);

        // r = sigmoid(x*wir + hr)          [both batches packed]
        u64 m = fmul2(ffma2(x2, wir2, hr2), negl2e2);
        unpack2(m, lo, hi);
        u64 d = fadd2(pack2(ex2f(lo), ex2f(hi)), one2);
        unpack2(d, lo, hi);
        const u64 r2 = pack2(rcpf(lo), rcpf(hi));
        // z = sigmoid(x*wiz + hz)
        m = fmul2(ffma2(x2, wiz2, hz2), negl2e2);
        unpack2(m, lo, hi);
        d = fadd2(pack2(ex2f(lo), ex2f(hi)), one2);
        unpack2(d, lo, hi);
        const u64 z2 = pack2(rcpf(lo), rcpf(hi));
        // n = tanh((x*win + bin) + r*hn) = 1 - 2/(exp(2u)+1)
        const u64 pn = ffma2(r2, hn2, ffma2(x2, win2, bin2));
        m = fmul2(pn, twol2e2);
        unpack2(m, lo, hi);
        d = fadd2(pack2(ex2f(lo), ex2f(hi)), one2);
        unpack2(d, lo, hi);
        const u64 inv = pack2(rcpf(lo), rcpf(hi));
        const u64 n2 = ffma2(negtwo2, inv, one2);
        // h = z*(h - n) + n    (negate n via sign-bit flip on the ALU pipe)
        const u64 negn = n2 ^ 0x8000000080000000ULL;
        hs2 = ffma2(z2, fadd2(hs2, negn), n2);

        // ---- exchange: parity double-buffer, ONE syncwarp ----
        unpack2(hs2, lo, hi);
        xch[p][0][lane] = lo;
        xch[p][1][lane] = hi;
        __syncwarp();
        const ulonglong2* q0 = reinterpret_cast<const ulonglong2*>(xch[p][0]);
        const ulonglong2* q1 = reinterpret_cast<const ulonglong2*>(xch[p][1]);
#pragma unroll
        for (int i = 0; i < 8; i++) {
            ulonglong2 v0 = q0[i]; h0[2*i] = v0.x; h0[2*i+1] = v0.y;
            ulonglong2 v1 = q1[i]; h1[2*i] = v1.x; h1[2*i+1] = v1.y;
        }
    };

    // ---- main scan, 4 steps per iter with float4 x prefetch ----
    const float4* x4A = reinterpret_cast<const float4*>(xA);
    const float4* x4B = reinterpret_cast<const float4*>(xB);
    const int nIt = T >> 2;
    float4 ca = x4A[0], cb = x4B[0];
    for (int it = 0; it < nIt; ++it) {
        int nx = (it + 1 < nIt) ? it + 1 : it;
        float4 na = x4A[nx], nb = x4B[nx];
        step(ca.x, cb.x, 0);
        step(ca.y, cb.y, 1);
        step(ca.z, cb.z, 0);
        step(ca.w, cb.w, 1);
        ca = na; cb = nb;
    }
    for (int t = nIt << 2; t < T; ++t) step(xA[t], xB[t], t & 1);   // T%4 remainder

    float hs0, hs1;
    unpack2(hs2, hs0, hs1);

    // ---- backward direction: exactly ONE step from h=0 on x[:, T-1] ----
    const float wibr = Wih_b[rr], wibz = Wih_b[rz], wibn = Wih_b[rn];
    const float bibr = bih_b[rr], bibz = bih_b[rz], bibn = bih_b[rn];
    const float bhbr = bhh_b[rr], bhbz = bhh_b[rz], bhbn = bhh_b[rn];
    const float xl0 = xA[T - 1], xl1 = xB[T - 1];

    float rb0 = sigm(fmaf(xl0, wibr, bibr) + bhbr);
    float zb0 = sigm(fmaf(xl0, wibz, bibz) + bhbz);
    float nb0 = tanh_fast(fmaf(rb0, bhbn, fmaf(xl0, wibn, bibn)));
    float hb0 = (1.0f - zb0) * nb0;

    float rb1 = sigm(fmaf(xl1, wibr, bibr) + bhbr);
    float zb1 = sigm(fmaf(xl1, wibz, bibz) + bhbz);
    float nb1 = tanh_fast(fmaf(rb1, bhbn, fmaf(xl1, wibn, bibn)));
    float hb1 = (1.0f - zb1) * nb1;

    // ---- MLP head ----
    scr[0][lane] = hs0; scr[0][32 + lane] = hb0;
    scr[1][lane] = hs1; scr[1][32 + lane] = hb1;
    __syncwarp();

    if (lane < 16) {
        const float4* w4 = reinterpret_cast<const float4*>(W1 + lane * 64);
        float a0 = b1v[lane], a1 = b1v[lane];
        const float* s0 = scr[0];
        const float* s1 = scr[1];
#pragma unroll
        for (int i = 0; i < 16; i++) {
            float4 w = w4[i];
            a0 = fmaf(w.x, s0[4*i], a0);   a0 = fmaf(w.y, s0[4*i+1], a0);
            a0 = fmaf(w.z, s0[4*i+2], a0); a0 = fmaf(w.w, s0[4*i+3], a0);
            a1 = fmaf(w.x, s1[4*i], a1);   a1 = fmaf(w.y, s1[4*i+1], a1);
            a1 = fmaf(w.z, s1[4*i+2], a1); a1 = fmaf(w.w, s1[4*i+3], a1);
        }
        scr[0][64 + lane] = fmaxf(a0, 0.0f);
        scr[1][64 + lane] = fmaxf(a1, 0.0f);
    }
    __syncwarp();

    float v0 = (lane < 16) ? W2[lane] * scr[0][64 + lane] : 0.0f;
    float v1 = (lane < 16) ? W2[lane] * scr[1][64 + lane] : 0.0f;
#pragma unroll
    for (int o = 16; o > 0; o >>= 1) {
        v0 += __shfl_xor_sync(FULLMASK, v0, o);
        v1 += __shfl_xor_sync(FULLMASK, v1, o);
    }
    if (lane == 0) {
        float bb2 = b2v[0];
        out[bA] = sigm(v0 + bb2);
        if (has2) out[bB] = sigm(v1 + bb2);
    }
}

extern "C" void kernel_launch(void* const* d_in, const int* in_sizes, int n_in,
                              void* d_out, int out_size) {
    const float* x     = (const float*)d_in[0];
    const float* Wih_f = (const float*)d_in[1];
    const float* Whh_f = (const float*)d_in[2];
    const float* bih_f = (const float*)d_in[3];
    const float* bhh_f = (const float*)d_in[4];
    const float* Wih_b = (const float*)d_in[5];
    // d_in[6] = W_hh_b: mathematically unused (backward output at T-1 starts from h=0)
    const float* bih_b = (const float*)d_in[7];
    const float* bhh_b = (const float*)d_in[8];
    const float* W1    = (const float*)d_in[9];
    const float* b1v   = (const float*)d_in[10];
    const float* W2    = (const float*)d_in[11];
    const float* b2v   = (const float*)d_in[12];

    int B = out_size;                // output [B,1] fp32
    int T = in_sizes[0] / B;         // x is [B,T,1]

    int grid = (B + 1) / 2;          // 2 batch rows per 1-warp block, single wave
    gru_bidir_kernel<<<grid, 32>>>(x, Wih_f, Whh_f, bih_f, bhh_f,
                                   Wih_b, bih_b, bhh_b,
                                   W1, b1v, W2, b2v,
                                   (float*)d_out, B, T);
}